// round 9
// baseline (speedup 1.0000x reference)
#include <cuda_runtime.h>
#include <cuda_bf16.h>
#include <cstdint>

#define NN 50000
#define DD 128
#define EE 800000
#define NBT 391           // ceil(50000/128) GEMM row tiles

typedef unsigned short ushortt;

// ---------------- scratch (device globals) ----------------
__device__ __align__(16) float g_h[NN * DD];
__device__ __align__(16) float g_x[NN * DD];
__device__ float g_psum[NBT * DD];
__device__ float g_psumsq[NBT * DD];
__device__ float g_scale[DD];
__device__ float g_shift[DD];
// CSR
__device__ int g_cnt[NN];
__device__ int g_row[NN + 1];
__device__ int g_cur[NN];
__device__ int g_adj[EE];
// W images, transposed to [n][k] row-major bf16, hi/lo split; 6 mats
__device__ __align__(16) __nv_bfloat16 g_whi[6 * 16384];
__device__ __align__(16) __nv_bfloat16 g_wlo[6 * 16384];

// ---------------- helpers ----------------
__device__ __forceinline__ uint32_t smem_u32(const void* p) {
    uint32_t a;
    asm("{ .reg .u64 t; cvta.to.shared.u64 t, %1; cvt.u32.u64 %0, t; }" : "=r"(a) : "l"(p));
    return a;
}
__device__ __forceinline__ uint32_t pack2bf(__nv_bfloat16 a, __nv_bfloat16 b) {
    return (uint32_t)__bfloat16_as_ushort(a) | ((uint32_t)__bfloat16_as_ushort(b) << 16);
}
__device__ __forceinline__ void ldm_x4(uint32_t addr, uint32_t* r) {
    asm volatile("ldmatrix.sync.aligned.m8n8.x4.shared.b16 {%0,%1,%2,%3}, [%4];"
        : "=r"(r[0]), "=r"(r[1]), "=r"(r[2]), "=r"(r[3]) : "r"(addr));
}
__device__ __forceinline__ void mma_bf16(float* d, const uint32_t* a, const uint32_t* b) {
    asm volatile("mma.sync.aligned.m16n8k16.row.col.f32.bf16.bf16.f32 "
        "{%0,%1,%2,%3}, {%4,%5,%6,%7}, {%8,%9}, {%0,%1,%2,%3};"
        : "+f"(d[0]), "+f"(d[1]), "+f"(d[2]), "+f"(d[3])
        : "r"(a[0]), "r"(a[1]), "r"(a[2]), "r"(a[3]), "r"(b[0]), "r"(b[1]));
}
__device__ __forceinline__ void cp16(uint32_t sm, const void* g) {
    asm volatile("cp.async.ca.shared.global [%0], [%1], 16;" :: "r"(sm), "l"(g));
}
#define CP_COMMIT() asm volatile("cp.async.commit_group;" ::: "memory")
#define CP_WAIT(n)  asm volatile("cp.async.wait_group %0;" :: "n"(n) : "memory")

#define PITCHF 136  // X planes: full 128 k-cols + 8 pad (272B rows: 8 distinct phases)
#define PITCHW 40   // W chunk planes (80B rows)
#define XHI 0
#define XLO 34816
#define WOFF 69632
#define WBUFS 20480         // per double-buffer slot (hi+lo planes)
#define SM_TOT 110592

// ---------------- CSR build ----------------
__global__ void k_zero_cnt() {
    int i = blockIdx.x * blockDim.x + threadIdx.x;
    if (i < NN) g_cnt[i] = 0;
}
__global__ void k_hist(const int* __restrict__ dst) {
    int e = blockIdx.x * blockDim.x + threadIdx.x;
    if (e < EE) atomicAdd(&g_cnt[dst[e]], 1);
}
__global__ void __launch_bounds__(1024) k_scan() {
    __shared__ int sm[1024];
    const int CH = 49;
    int t = threadIdx.x;
    int beg = t * CH;
    int tot = 0;
    for (int i = beg; i < beg + CH && i < NN; i++) tot += g_cnt[i];
    sm[t] = tot;
    __syncthreads();
    for (int off = 1; off < 1024; off <<= 1) {
        int v = (t >= off) ? sm[t - off] : 0;
        __syncthreads();
        sm[t] += v;
        __syncthreads();
    }
    int base = sm[t] - tot;
    for (int i = beg; i < beg + CH && i < NN; i++) {
        g_row[i] = base; g_cur[i] = 0; base += g_cnt[i];
    }
    if (t == 1023) g_row[NN] = sm[1023];
}
__global__ void k_fill(const int* __restrict__ src, const int* __restrict__ dst) {
    int e = blockIdx.x * blockDim.x + threadIdx.x;
    if (e >= EE) return;
    int d = dst[e];
    int pos = atomicAdd(&g_cur[d], 1);
    g_adj[g_row[d] + pos] = src[e];
}

// ---------------- weight prep ----------------
__global__ void __launch_bounds__(256) k_wprep(const float* __restrict__ W1,
                                               const float* __restrict__ W2) {
    int m = blockIdx.x;
    const float* src = (m < 3) ? (W1 + m * 16384) : (W2 + (m - 3) * 16384);
    __nv_bfloat16* hi = g_whi + m * 16384;
    __nv_bfloat16* lo = g_wlo + m * 16384;
    for (int i = threadIdx.x; i < 16384; i += 256) {
        int k = i >> 7, n = i & 127;
        float v = src[i];
        __nv_bfloat16 h = __float2bfloat16(v);
        __nv_bfloat16 l = __float2bfloat16(v - __bfloat162float(h));
        hi[n * 128 + k] = h;
        lo[n * 128 + k] = l;
    }
}

// ---------------- shared GEMM machinery ----------------
__device__ __forceinline__ void prefetch_w(char* sm, int buf, int mat, int ck) {
    int tid = threadIdx.x;
    const __nv_bfloat16* gh = g_whi + mat * 16384 + ck * 32;
    const __nv_bfloat16* gl = g_wlo + mat * 16384 + ck * 32;
    uint32_t sh = smem_u32(sm + WOFF + buf * WBUFS);
    uint32_t sl = sh + 10240;
    for (int i = tid; i < 512; i += 256) {
        int row = i >> 2, q = i & 3;
        uint32_t so = (uint32_t)(row * PITCHW + q * 8) * 2;
        cp16(sh + so, gh + row * 128 + q * 8);
        cp16(sl + so, gl + row * 128 + q * 8);
    }
}

__device__ __forceinline__ void do_pass(uint32_t abase, uint32_t bbase, int kofs,
                                        int wm, int wn, int lane, float acc[4][4][4]) {
    #pragma unroll
    for (int ks = 0; ks < 2; ks++) {
        uint32_t af[4][4];
        #pragma unroll
        for (int mt = 0; mt < 4; mt++) {
            int row = wm * 64 + mt * 16 + (lane & 7) + ((lane >> 3) & 1) * 8;
            int col = kofs + ks * 16 + ((lane >> 4) & 1) * 8;
            ldm_x4(abase + (row * PITCHF + col) * 2, af[mt]);
        }
        uint32_t bf[4][2];
        #pragma unroll
        for (int jp = 0; jp < 2; jp++) {
            int n = wn * 32 + jp * 16 + ((lane >> 4) & 1) * 8 + (lane & 7);
            int col = ks * 16 + ((lane >> 3) & 1) * 8;
            uint32_t r4[4];
            ldm_x4(bbase + (n * PITCHW + col) * 2, r4);
            bf[jp * 2][0] = r4[0]; bf[jp * 2][1] = r4[1];
            bf[jp * 2 + 1][0] = r4[2]; bf[jp * 2 + 1][1] = r4[3];
        }
        #pragma unroll
        for (int mt = 0; mt < 4; mt++)
            #pragma unroll
            for (int nt = 0; nt < 4; nt++)
                mma_bf16(acc[mt][nt], af[mt], bf[nt]);
    }
}

// W-pipelined mainloop over 4 k-chunks, X planes already resident
__device__ __forceinline__ void gemm_mainloop(char* sm, int mat, int wm, int wn,
                                              int lane, float acc[4][4][4]) {
    uint32_t axh = smem_u32(sm + XHI);
    uint32_t axl = smem_u32(sm + XLO);
    int buf = 0;
    for (int ck = 0; ck < 4; ck++) {
        if (ck < 3) {
            prefetch_w(sm, buf ^ 1, mat, ck + 1);
            CP_COMMIT();
            CP_WAIT(1);
        } else {
            CP_WAIT(0);
        }
        __syncthreads();
        uint32_t bwh = smem_u32(sm + WOFF + buf * WBUFS);
        uint32_t bwl = bwh + 10240;
        int kofs = ck * 32;
        do_pass(axh, bwh, kofs, wm, wn, lane, acc);   // hi*hi
        do_pass(axh, bwl, kofs, wm, wn, lane, acc);   // hi*lo
        do_pass(axl, bwh, kofs, wm, wn, lane, acc);   // lo*hi
        __syncthreads();
        buf ^= 1;
    }
}

extern __shared__ __align__(16) char dsm[];

// ---------------- GEMM1 fused with gather+combine ----------------
__global__ void __launch_bounds__(256) k_gemm1_f(const float* __restrict__ Xext, int use_ext,
                                                 const float* __restrict__ epsp,
                                                 int mat, const float* __restrict__ b) {
    char* sm = dsm;
    const float* X = use_ext ? Xext : (const float*)g_x;
    int tid = threadIdx.x;
    int wid = tid >> 5, lane = tid & 31;
    int wm = wid & 1, wn = wid >> 1;
    int row0 = blockIdx.x * 128;

    // kick off first W prefetch immediately (disjoint smem region)
    prefetch_w(sm, 0, mat, 0);
    CP_COMMIT();

    // gather + combine + bf16 split -> X planes (warp per node, 16 nodes/warp)
    float eps1 = 1.f + epsp[0];
    ushortt* xhi = (ushortt*)(sm + XHI);
    ushortt* xlo = (ushortt*)(sm + XLO);
    for (int ii = 0; ii < 16; ii++) {
        int r = wid * 16 + ii;
        int node = row0 + r;
        uint2 hv = make_uint2(0u, 0u), lv = make_uint2(0u, 0u);
        if (node < NN) {
            int beg = g_row[node], end = g_row[node + 1];
            float4 a = make_float4(0.f, 0.f, 0.f, 0.f);
            #pragma unroll 2
            for (int i = beg; i < end; i++) {
                int s = g_adj[i];
                float4 v = ((const float4*)X)[s * 32 + lane];
                a.x += v.x; a.y += v.y; a.z += v.z; a.w += v.w;
            }
            float4 xv = ((const float4*)X)[node * 32 + lane];
            float pa = a.x * a.x + a.y * a.y + a.z * a.z + a.w * a.w;
            float px = xv.x * xv.x + xv.y * xv.y + xv.z * xv.z + xv.w * xv.w;
            #pragma unroll
            for (int off = 16; off; off >>= 1) {
                pa += __shfl_xor_sync(0xffffffffu, pa, off);
                px += __shfl_xor_sync(0xffffffffu, px, off);
            }
            float ia = 1.f / fmaxf(sqrtf(pa), 1e-12f);
            float ix = eps1 / fmaxf(sqrtf(px), 1e-12f);
            float o[4];
            o[0] = a.x * ia + xv.x * ix;
            o[1] = a.y * ia + xv.y * ix;
            o[2] = a.z * ia + xv.z * ix;
            o[3] = a.w * ia + xv.w * ix;
            __nv_bfloat16 h[4], l[4];
            #pragma unroll
            for (int j = 0; j < 4; j++) {
                h[j] = __float2bfloat16(o[j]);
                l[j] = __float2bfloat16(o[j] - __bfloat162float(h[j]));
            }
            hv = make_uint2(pack2bf(h[0], h[1]), pack2bf(h[2], h[3]));
            lv = make_uint2(pack2bf(l[0], l[1]), pack2bf(l[2], l[3]));
        }
        *(uint2*)(xhi + r * PITCHF + lane * 4) = hv;
        *(uint2*)(xlo + r * PITCHF + lane * 4) = lv;
    }
    __syncthreads();

    float acc[4][4][4];
    #pragma unroll
    for (int mt = 0; mt < 4; mt++)
        #pragma unroll
        for (int nt = 0; nt < 4; nt++)
            #pragma unroll
            for (int i = 0; i < 4; i++) acc[mt][nt][i] = 0.f;

    gemm_mainloop(sm, mat, wm, wn, lane, acc);

    // epilogue: bias, store h, BN partials (validated in R8)
    float ls[4][2], lq[4][2];
    #pragma unroll
    for (int nt = 0; nt < 4; nt++) { ls[nt][0] = ls[nt][1] = lq[nt][0] = lq[nt][1] = 0.f; }
    #pragma unroll
    for (int mt = 0; mt < 4; mt++) {
        int r0 = row0 + wm * 64 + mt * 16 + (lane >> 2);
        int r1 = r0 + 8;
        #pragma unroll
        for (int nt = 0; nt < 4; nt++) {
            int c = wn * 32 + nt * 8 + (lane & 3) * 2;
            float b0 = b[c], b1 = b[c + 1];
            float v0 = acc[mt][nt][0] + b0, v1 = acc[mt][nt][1] + b1;
            float v2 = acc[mt][nt][2] + b0, v3 = acc[mt][nt][3] + b1;
            if (r0 < NN) {
                *(float2*)(g_h + r0 * DD + c) = make_float2(v0, v1);
                ls[nt][0] += v0; ls[nt][1] += v1;
                lq[nt][0] += v0 * v0; lq[nt][1] += v1 * v1;
            }
            if (r1 < NN) {
                *(float2*)(g_h + r1 * DD + c) = make_float2(v2, v3);
                ls[nt][0] += v2; ls[nt][1] += v3;
                lq[nt][0] += v2 * v2; lq[nt][1] += v3 * v3;
            }
        }
    }
    #pragma unroll
    for (int off = 4; off <= 16; off <<= 1) {
        #pragma unroll
        for (int nt = 0; nt < 4; nt++) {
            ls[nt][0] += __shfl_xor_sync(0xffffffffu, ls[nt][0], off);
            ls[nt][1] += __shfl_xor_sync(0xffffffffu, ls[nt][1], off);
            lq[nt][0] += __shfl_xor_sync(0xffffffffu, lq[nt][0], off);
            lq[nt][1] += __shfl_xor_sync(0xffffffffu, lq[nt][1], off);
        }
    }
    __syncthreads();   // done with W region; reuse for stats
    float* ssum = (float*)(sm + WOFF);
    float* ssq  = ssum + 256;
    if (lane < 4) {
        #pragma unroll
        for (int nt = 0; nt < 4; nt++) {
            ssum[wid * 32 + nt * 8 + lane * 2]     = ls[nt][0];
            ssum[wid * 32 + nt * 8 + lane * 2 + 1] = ls[nt][1];
            ssq[wid * 32 + nt * 8 + lane * 2]      = lq[nt][0];
            ssq[wid * 32 + nt * 8 + lane * 2 + 1]  = lq[nt][1];
        }
    }
    __syncthreads();
    if (tid < DD) {
        int w0 = (tid >> 5) * 2;
        float s = ssum[w0 * 32 + (tid & 31)] + ssum[(w0 + 1) * 32 + (tid & 31)];
        float q = ssq[w0 * 32 + (tid & 31)] + ssq[(w0 + 1) * 32 + (tid & 31)];
        g_psum[blockIdx.x * DD + tid] = s;
        g_psumsq[blockIdx.x * DD + tid] = q;
    }
}

// ---------------- finalize BN ----------------
__global__ void __launch_bounds__(256) k_finalize(const float* __restrict__ gamma,
                                                  const float* __restrict__ beta) {
    __shared__ float ss[256], sq[256];
    int c = blockIdx.x;
    int t = threadIdx.x;
    float s = 0.f, q = 0.f;
    for (int bk = t; bk < NBT; bk += 256) {
        s += g_psum[bk * DD + c];
        q += g_psumsq[bk * DD + c];
    }
    ss[t] = s; sq[t] = q;
    __syncthreads();
    for (int off = 128; off; off >>= 1) {
        if (t < off) { ss[t] += ss[t + off]; sq[t] += sq[t + off]; }
        __syncthreads();
    }
    if (t == 0) {
        float mean = ss[0] * (1.f / NN);
        float var  = sq[0] * (1.f / NN) - mean * mean;
        float sc = gamma[c] * rsqrtf(var + 1e-5f);
        g_scale[c] = sc;
        g_shift[c] = beta[c] - mean * sc;
    }
}

// ---------------- GEMM2 fused with BN+ReLU ----------------
__global__ void __launch_bounds__(256) k_gemm2_f(int mat, const float* __restrict__ b,
                                                 float* __restrict__ OutExt,
                                                 int internal, int do_relu) {
    char* sm = dsm;
    float* Out = internal ? (float*)g_x : OutExt;
    int tid = threadIdx.x;
    int wid = tid >> 5, lane = tid & 31;
    int wm = wid & 1, wn = wid >> 1;
    int row0 = blockIdx.x * 128;

    prefetch_w(sm, 0, mat, 0);
    CP_COMMIT();

    // X planes: bn_relu(g_h) split, full 128 cols
    {
        int r = tid >> 1, half = tid & 1;
        int gr = row0 + r;
        ushortt* xhi = (ushortt*)(sm + XHI) + r * PITCHF + half * 64;
        ushortt* xlo = (ushortt*)(sm + XLO) + r * PITCHF + half * 64;
        #pragma unroll
        for (int gq = 0; gq < 8; gq++) {
            int gc = half * 64 + gq * 8;
            uint4 hv = make_uint4(0, 0, 0, 0), lv = make_uint4(0, 0, 0, 0);
            if (gr < NN) {
                const float* srcp = g_h + gr * DD + gc;
                uint32_t hp[4], lp[4];
                #pragma unroll
                for (int i = 0; i < 4; i++) {
                    float v0 = fmaxf(fmaf(srcp[2 * i], g_scale[gc + 2 * i], g_shift[gc + 2 * i]), 0.f);
                    float v1 = fmaxf(fmaf(srcp[2 * i + 1], g_scale[gc + 2 * i + 1], g_shift[gc + 2 * i + 1]), 0.f);
                    __nv_bfloat16 h0 = __float2bfloat16(v0), h1 = __float2bfloat16(v1);
                    __nv_bfloat16 l0 = __float2bfloat16(v0 - __bfloat162float(h0));
                    __nv_bfloat16 l1 = __float2bfloat16(v1 - __bfloat162float(h1));
                    hp[i] = pack2bf(h0, h1);
                    lp[i] = pack2bf(l0, l1);
                }
                hv = make_uint4(hp[0], hp[1], hp[2], hp[3]);
                lv = make_uint4(lp[0], lp[1], lp[2], lp[3]);
            }
            *(uint4*)(xhi + gq * 8) = hv;
            *(uint4*)(xlo + gq * 8) = lv;
        }
    }
    __syncthreads();

    float acc[4][4][4];
    #pragma unroll
    for (int mt = 0; mt < 4; mt++)
        #pragma unroll
        for (int nt = 0; nt < 4; nt++)
            #pragma unroll
            for (int i = 0; i < 4; i++) acc[mt][nt][i] = 0.f;

    gemm_mainloop(sm, mat, wm, wn, lane, acc);

    #pragma unroll
    for (int mt = 0; mt < 4; mt++) {
        int r0 = row0 + wm * 64 + mt * 16 + (lane >> 2);
        int r1 = r0 + 8;
        #pragma unroll
        for (int nt = 0; nt < 4; nt++) {
            int c = wn * 32 + nt * 8 + (lane & 3) * 2;
            float b0 = b[c], b1 = b[c + 1];
            float v0 = acc[mt][nt][0] + b0, v1 = acc[mt][nt][1] + b1;
            float v2 = acc[mt][nt][2] + b0, v3 = acc[mt][nt][3] + b1;
            if (do_relu) {
                v0 = fmaxf(v0, 0.f); v1 = fmaxf(v1, 0.f);
                v2 = fmaxf(v2, 0.f); v3 = fmaxf(v3, 0.f);
            }
            if (r0 < NN) *(float2*)(Out + r0 * DD + c) = make_float2(v0, v1);
            if (r1 < NN) *(float2*)(Out + r1 * DD + c) = make_float2(v2, v3);
        }
    }
}

extern "C" void kernel_launch(void* const* d_in, const int* in_sizes, int n_in,
                              void* d_out, int out_size) {
    (void)in_sizes; (void)n_in; (void)out_size;
    const float* x     = (const float*)d_in[0];
    const int*   ei    = (const int*)d_in[1];   // int32 (JAX x64 disabled)
    const float* W1    = (const float*)d_in[2];
    const float* b1    = (const float*)d_in[3];
    const float* gamma = (const float*)d_in[4];
    const float* beta  = (const float*)d_in[5];
    const float* W2    = (const float*)d_in[6];
    const float* b2    = (const float*)d_in[7];
    const float* eps   = (const float*)d_in[8];
    float* out = (float*)d_out;

    const int* src = ei;
    const int* dst = ei + EE;

    cudaFuncSetAttribute(k_gemm1_f, cudaFuncAttributeMaxDynamicSharedMemorySize, SM_TOT);
    cudaFuncSetAttribute(k_gemm2_f, cudaFuncAttributeMaxDynamicSharedMemorySize, SM_TOT);

    k_zero_cnt<<<(NN + 255) / 256, 256>>>();
    k_hist<<<(EE + 255) / 256, 256>>>(dst);
    k_scan<<<1, 1024>>>();
    k_fill<<<(EE + 255) / 256, 256>>>(src, dst);
    k_wprep<<<6, 256>>>(W1, W2);

    for (int l = 0; l < 3; l++) {
        int use_ext = (l == 0) ? 1 : 0;
        int internal = (l == 2) ? 0 : 1;
        k_gemm1_f<<<NBT, 256, SM_TOT>>>(x, use_ext, eps + l, l, b1 + l * DD);
        k_finalize<<<DD, 256>>>(gamma + l * DD, beta + l * DD);
        k_gemm2_f<<<NBT, 256, SM_TOT>>>(3 + l, b2 + l * DD, out, internal, (l < 2) ? 1 : 0);
    }
}

// round 10
// speedup vs baseline: 1.6312x; 1.6312x over previous
#include <cuda_runtime.h>
#include <cuda_bf16.h>
#include <cstdint>

#define NN 50000
#define DD 128
#define EE 800000
#define NBT 391           // ceil(50000/128) GEMM row tiles

typedef unsigned short ushortt;

// ---------------- scratch (device globals) ----------------
__device__ __align__(16) float g_h[NN * DD];
__device__ __align__(16) float g_x[NN * DD];
__device__ __align__(16) __nv_bfloat16 g_xhi[NN * DD];  // combined feat, bf16 hi plane
__device__ __align__(16) __nv_bfloat16 g_xlo[NN * DD];  // combined feat, bf16 lo plane
__device__ float g_psum[NBT * DD];
__device__ float g_psumsq[NBT * DD];
__device__ float g_scale[DD];
__device__ float g_shift[DD];
// CSR
__device__ int g_cnt[NN];
__device__ int g_row[NN + 1];
__device__ int g_cur[NN];
__device__ int g_adj[EE];
// W images, transposed to [n][k] row-major bf16, hi/lo split; 6 mats
__device__ __align__(16) __nv_bfloat16 g_whi[6 * 16384];
__device__ __align__(16) __nv_bfloat16 g_wlo[6 * 16384];

// ---------------- helpers ----------------
__device__ __forceinline__ uint32_t smem_u32(const void* p) {
    uint32_t a;
    asm("{ .reg .u64 t; cvta.to.shared.u64 t, %1; cvt.u32.u64 %0, t; }" : "=r"(a) : "l"(p));
    return a;
}
__device__ __forceinline__ uint32_t pack2bf(__nv_bfloat16 a, __nv_bfloat16 b) {
    return (uint32_t)__bfloat16_as_ushort(a) | ((uint32_t)__bfloat16_as_ushort(b) << 16);
}
__device__ __forceinline__ void ldm_x4(uint32_t addr, uint32_t* r) {
    asm volatile("ldmatrix.sync.aligned.m8n8.x4.shared.b16 {%0,%1,%2,%3}, [%4];"
        : "=r"(r[0]), "=r"(r[1]), "=r"(r[2]), "=r"(r[3]) : "r"(addr));
}
__device__ __forceinline__ void mma_bf16(float* d, const uint32_t* a, const uint32_t* b) {
    asm volatile("mma.sync.aligned.m16n8k16.row.col.f32.bf16.bf16.f32 "
        "{%0,%1,%2,%3}, {%4,%5,%6,%7}, {%8,%9}, {%0,%1,%2,%3};"
        : "+f"(d[0]), "+f"(d[1]), "+f"(d[2]), "+f"(d[3])
        : "r"(a[0]), "r"(a[1]), "r"(a[2]), "r"(a[3]), "r"(b[0]), "r"(b[1]));
}
__device__ __forceinline__ void cp16(uint32_t sm, const void* g) {
    asm volatile("cp.async.ca.shared.global [%0], [%1], 16;" :: "r"(sm), "l"(g));
}
#define CP_COMMIT() asm volatile("cp.async.commit_group;" ::: "memory")
#define CP_WAIT(n)  asm volatile("cp.async.wait_group %0;" :: "n"(n) : "memory")

#define PITCH 40                 // bf16 per smem plane row (80B: conflict-free ldmatrix)
#define PS 10240                 // plane bytes: 128*PITCH*2
// GEMM1 smem: [Xhi|Xlo](buf0) [Xhi|Xlo](buf1) [Whi|Wlo](buf0) [Whi|Wlo](buf1)
#define X_OFF(b)  ((b) * 2 * PS)
#define W_OFF1(b) (4 * PS + (b) * 2 * PS)
#define SM1_TOT   (8 * PS)       // 81920
// GEMM2 smem: [Xhi|Xlo] [Whi|Wlo](buf0) [Whi|Wlo](buf1)
#define W_OFF2(b) (2 * PS + (b) * 2 * PS)
#define SM2_TOT   (6 * PS)       // 61440

// ---------------- CSR build ----------------
__global__ void k_zero_cnt() {
    int i = blockIdx.x * blockDim.x + threadIdx.x;
    if (i < NN) g_cnt[i] = 0;
}
__global__ void k_hist(const int* __restrict__ dst) {
    int e = blockIdx.x * blockDim.x + threadIdx.x;
    if (e < EE) atomicAdd(&g_cnt[dst[e]], 1);
}
__global__ void __launch_bounds__(1024) k_scan() {
    __shared__ int sm[1024];
    const int CH = 49;
    int t = threadIdx.x;
    int beg = t * CH;
    int tot = 0;
    for (int i = beg; i < beg + CH && i < NN; i++) tot += g_cnt[i];
    sm[t] = tot;
    __syncthreads();
    for (int off = 1; off < 1024; off <<= 1) {
        int v = (t >= off) ? sm[t - off] : 0;
        __syncthreads();
        sm[t] += v;
        __syncthreads();
    }
    int base = sm[t] - tot;
    for (int i = beg; i < beg + CH && i < NN; i++) {
        g_row[i] = base; g_cur[i] = 0; base += g_cnt[i];
    }
    if (t == 1023) g_row[NN] = sm[1023];
}
__global__ void k_fill(const int* __restrict__ src, const int* __restrict__ dst) {
    int e = blockIdx.x * blockDim.x + threadIdx.x;
    if (e >= EE) return;
    int d = dst[e];
    int pos = atomicAdd(&g_cur[d], 1);
    g_adj[g_row[d] + pos] = src[e];
}

// ---------------- weight prep ----------------
__global__ void __launch_bounds__(256) k_wprep(const float* __restrict__ W1,
                                               const float* __restrict__ W2) {
    int m = blockIdx.x;
    const float* src = (m < 3) ? (W1 + m * 16384) : (W2 + (m - 3) * 16384);
    __nv_bfloat16* hi = g_whi + m * 16384;
    __nv_bfloat16* lo = g_wlo + m * 16384;
    for (int i = threadIdx.x; i < 16384; i += 256) {
        int k = i >> 7, n = i & 127;
        float v = src[i];
        __nv_bfloat16 h = __float2bfloat16(v);
        __nv_bfloat16 l = __float2bfloat16(v - __bfloat162float(h));
        hi[n * 128 + k] = h;
        lo[n * 128 + k] = l;
    }
}

// ---------------- gather + combine -> bf16 hi/lo planes (validated math) ----------------
__global__ void k_gather(const float* __restrict__ Xext, int use_ext,
                         const float* __restrict__ epsp) {
    const float* X = use_ext ? Xext : (const float*)g_x;
    int gid = blockIdx.x * blockDim.x + threadIdx.x;
    int node = gid >> 5;
    if (node >= NN) return;
    int lane = gid & 31;
    int beg = g_row[node], end = g_row[node + 1];
    float4 a = make_float4(0.f, 0.f, 0.f, 0.f);
    for (int i = beg; i < end; i++) {
        int s = g_adj[i];
        float4 v = ((const float4*)X)[s * 32 + lane];
        a.x += v.x; a.y += v.y; a.z += v.z; a.w += v.w;
    }
    float4 xv = ((const float4*)X)[node * 32 + lane];
    float pa = a.x * a.x + a.y * a.y + a.z * a.z + a.w * a.w;
    float px = xv.x * xv.x + xv.y * xv.y + xv.z * xv.z + xv.w * xv.w;
    #pragma unroll
    for (int off = 16; off; off >>= 1) {
        pa += __shfl_xor_sync(0xffffffffu, pa, off);
        px += __shfl_xor_sync(0xffffffffu, px, off);
    }
    float ia = 1.f / fmaxf(sqrtf(pa), 1e-12f);
    float ix = (1.f + epsp[0]) / fmaxf(sqrtf(px), 1e-12f);
    float o[4];
    o[0] = a.x * ia + xv.x * ix;
    o[1] = a.y * ia + xv.y * ix;
    o[2] = a.z * ia + xv.z * ix;
    o[3] = a.w * ia + xv.w * ix;
    __nv_bfloat16 h[4], l[4];
    #pragma unroll
    for (int j = 0; j < 4; j++) {
        h[j] = __float2bfloat16(o[j]);
        l[j] = __float2bfloat16(o[j] - __bfloat162float(h[j]));
    }
    *(uint2*)(g_xhi + node * DD + lane * 4) = make_uint2(pack2bf(h[0], h[1]), pack2bf(h[2], h[3]));
    *(uint2*)(g_xlo + node * DD + lane * 4) = make_uint2(pack2bf(l[0], l[1]), pack2bf(l[2], l[3]));
}

// ---------------- shared GEMM machinery (frag mapping identical to validated R8) ----------------
__device__ __forceinline__ void prefetch_w(char* sm, uint32_t woff, int mat, int ck) {
    int tid = threadIdx.x;
    const __nv_bfloat16* gh = g_whi + mat * 16384 + ck * 32;
    const __nv_bfloat16* gl = g_wlo + mat * 16384 + ck * 32;
    uint32_t sh = smem_u32(sm + woff);
    uint32_t sl = sh + PS;
    for (int i = tid; i < 512; i += 256) {
        int row = i >> 2, q = i & 3;
        uint32_t so = (uint32_t)(row * PITCH + q * 8) * 2;
        cp16(sh + so, gh + row * 128 + q * 8);
        cp16(sl + so, gl + row * 128 + q * 8);
    }
}

__device__ __forceinline__ void prefetch_x(char* sm, uint32_t xoff, int row0, int ck) {
    int tid = threadIdx.x;
    uint32_t sh = smem_u32(sm + xoff);
    uint32_t sl = sh + PS;
    for (int i = tid; i < 512; i += 256) {
        int row = i >> 2, q = i & 3;
        int gr = row0 + row;
        uint32_t so = (uint32_t)(row * PITCH + q * 8) * 2;
        if (gr < NN) {
            cp16(sh + so, g_xhi + gr * DD + ck * 32 + q * 8);
            cp16(sl + so, g_xlo + gr * DD + ck * 32 + q * 8);
        } else {
            uint4 z = make_uint4(0, 0, 0, 0);
            *(uint4*)((char*)nullptr + 0, (uint4*)0);  // placeholder removed below
        }
    }
}

__device__ __forceinline__ void prefetch_x_guarded(char* sm, uint32_t xoff, int row0, int ck) {
    int tid = threadIdx.x;
    uint32_t sh = smem_u32(sm + xoff);
    uint32_t sl = sh + PS;
    for (int i = tid; i < 512; i += 256) {
        int row = i >> 2, q = i & 3;
        int gr = row0 + row;
        uint32_t so = (uint32_t)(row * PITCH + q * 8) * 2;
        if (gr < NN) {
            cp16(sh + so, g_xhi + gr * DD + ck * 32 + q * 8);
            cp16(sl + so, g_xlo + gr * DD + ck * 32 + q * 8);
        } else {
            uint4 z = make_uint4(0, 0, 0, 0);
            *(uint4*)(sm + xoff + so) = z;
            *(uint4*)(sm + xoff + PS + so) = z;
        }
    }
}

__device__ __forceinline__ void do_pass(uint32_t abase, uint32_t bbase,
                                        int wm, int wn, int lane, float acc[4][4][4]) {
    #pragma unroll
    for (int ks = 0; ks < 2; ks++) {
        uint32_t af[4][4];
        #pragma unroll
        for (int mt = 0; mt < 4; mt++) {
            int row = wm * 64 + mt * 16 + (lane & 7) + ((lane >> 3) & 1) * 8;
            int col = ks * 16 + ((lane >> 4) & 1) * 8;
            ldm_x4(abase + (row * PITCH + col) * 2, af[mt]);
        }
        uint32_t bf[4][2];
        #pragma unroll
        for (int jp = 0; jp < 2; jp++) {
            int n = wn * 32 + jp * 16 + ((lane >> 4) & 1) * 8 + (lane & 7);
            int col = ks * 16 + ((lane >> 3) & 1) * 8;
            uint32_t r4[4];
            ldm_x4(bbase + (n * PITCH + col) * 2, r4);
            bf[jp * 2][0] = r4[0]; bf[jp * 2][1] = r4[1];
            bf[jp * 2 + 1][0] = r4[2]; bf[jp * 2 + 1][1] = r4[3];
        }
        #pragma unroll
        for (int mt = 0; mt < 4; mt++)
            #pragma unroll
            for (int nt = 0; nt < 4; nt++)
                mma_bf16(acc[mt][nt], af[mt], bf[nt]);
    }
}

extern __shared__ __align__(16) char dsm[];

// ---------------- GEMM1: h = comb @ W1 + b1 -> g_h, BN partials ----------------
__global__ void __launch_bounds__(256) k_gemm1_p(int mat, const float* __restrict__ b) {
    char* sm = dsm;
    int tid = threadIdx.x;
    int wid = tid >> 5, lane = tid & 31;
    int wm = wid & 1, wn = wid >> 1;
    int row0 = blockIdx.x * 128;

    float acc[4][4][4];
    #pragma unroll
    for (int mt = 0; mt < 4; mt++)
        #pragma unroll
        for (int nt = 0; nt < 4; nt++)
            #pragma unroll
            for (int i = 0; i < 4; i++) acc[mt][nt][i] = 0.f;

    prefetch_x_guarded(sm, X_OFF(0), row0, 0);
    prefetch_w(sm, W_OFF1(0), mat, 0);
    CP_COMMIT();

    int buf = 0;
    for (int ck = 0; ck < 4; ck++) {
        __syncthreads();   // all warps done reading planes of buf^1 (prev iter)
        if (ck < 3) {
            prefetch_x_guarded(sm, X_OFF(buf ^ 1), row0, ck + 1);
            prefetch_w(sm, W_OFF1(buf ^ 1), mat, ck + 1);
            CP_COMMIT();
            CP_WAIT(1);
        } else {
            CP_WAIT(0);
        }
        __syncthreads();
        uint32_t axh = smem_u32(sm + X_OFF(buf));
        uint32_t axl = axh + PS;
        uint32_t bwh = smem_u32(sm + W_OFF1(buf));
        uint32_t bwl = bwh + PS;
        do_pass(axh, bwh, wm, wn, lane, acc);   // hi*hi
        do_pass(axh, bwl, wm, wn, lane, acc);   // hi*lo
        do_pass(axl, bwh, wm, wn, lane, acc);   // lo*hi
        buf ^= 1;
    }

    // epilogue (validated R8): bias, store h, BN partials
    float ls[4][2], lq[4][2];
    #pragma unroll
    for (int nt = 0; nt < 4; nt++) { ls[nt][0] = ls[nt][1] = lq[nt][0] = lq[nt][1] = 0.f; }
    #pragma unroll
    for (int mt = 0; mt < 4; mt++) {
        int r0 = row0 + wm * 64 + mt * 16 + (lane >> 2);
        int r1 = r0 + 8;
        #pragma unroll
        for (int nt = 0; nt < 4; nt++) {
            int c = wn * 32 + nt * 8 + (lane & 3) * 2;
            float b0 = b[c], b1 = b[c + 1];
            float v0 = acc[mt][nt][0] + b0, v1 = acc[mt][nt][1] + b1;
            float v2 = acc[mt][nt][2] + b0, v3 = acc[mt][nt][3] + b1;
            if (r0 < NN) {
                *(float2*)(g_h + r0 * DD + c) = make_float2(v0, v1);
                ls[nt][0] += v0; ls[nt][1] += v1;
                lq[nt][0] += v0 * v0; lq[nt][1] += v1 * v1;
            }
            if (r1 < NN) {
                *(float2*)(g_h + r1 * DD + c) = make_float2(v2, v3);
                ls[nt][0] += v2; ls[nt][1] += v3;
                lq[nt][0] += v2 * v2; lq[nt][1] += v3 * v3;
            }
        }
    }
    #pragma unroll
    for (int off = 4; off <= 16; off <<= 1) {
        #pragma unroll
        for (int nt = 0; nt < 4; nt++) {
            ls[nt][0] += __shfl_xor_sync(0xffffffffu, ls[nt][0], off);
            ls[nt][1] += __shfl_xor_sync(0xffffffffu, ls[nt][1], off);
            lq[nt][0] += __shfl_xor_sync(0xffffffffu, lq[nt][0], off);
            lq[nt][1] += __shfl_xor_sync(0xffffffffu, lq[nt][1], off);
        }
    }
    __syncthreads();
    float* ssum = (float*)sm;
    float* ssq  = ssum + 256;
    if (lane < 4) {
        #pragma unroll
        for (int nt = 0; nt < 4; nt++) {
            ssum[wid * 32 + nt * 8 + lane * 2]     = ls[nt][0];
            ssum[wid * 32 + nt * 8 + lane * 2 + 1] = ls[nt][1];
            ssq[wid * 32 + nt * 8 + lane * 2]      = lq[nt][0];
            ssq[wid * 32 + nt * 8 + lane * 2 + 1]  = lq[nt][1];
        }
    }
    __syncthreads();
    if (tid < DD) {
        int w0 = (tid >> 5) * 2;
        float s = ssum[w0 * 32 + (tid & 31)] + ssum[(w0 + 1) * 32 + (tid & 31)];
        float q = ssq[w0 * 32 + (tid & 31)] + ssq[(w0 + 1) * 32 + (tid & 31)];
        g_psum[blockIdx.x * DD + tid] = s;
        g_psumsq[blockIdx.x * DD + tid] = q;
    }
}

// ---------------- finalize BN ----------------
__global__ void __launch_bounds__(256) k_finalize(const float* __restrict__ gamma,
                                                  const float* __restrict__ beta) {
    __shared__ float ss[256], sq[256];
    int c = blockIdx.x;
    int t = threadIdx.x;
    float s = 0.f, q = 0.f;
    for (int bk = t; bk < NBT; bk += 256) {
        s += g_psum[bk * DD + c];
        q += g_psumsq[bk * DD + c];
    }
    ss[t] = s; sq[t] = q;
    __syncthreads();
    for (int off = 128; off; off >>= 1) {
        if (t < off) { ss[t] += ss[t + off]; sq[t] += sq[t + off]; }
        __syncthreads();
    }
    if (t == 0) {
        float mean = ss[0] * (1.f / NN);
        float var  = sq[0] * (1.f / NN) - mean * mean;
        float sc = gamma[c] * rsqrtf(var + 1e-5f);
        g_scale[c] = sc;
        g_shift[c] = beta[c] - mean * sc;
    }
}

// ---------------- GEMM2: out = relu?(bn_relu(h) @ W2 + b2), W pipelined ----------------
__global__ void __launch_bounds__(256) k_gemm2_p(int mat, const float* __restrict__ b,
                                                 float* __restrict__ OutExt,
                                                 int internal, int do_relu) {
    char* sm = dsm;
    float* Out = internal ? (float*)g_x : OutExt;
    int tid = threadIdx.x;
    int wid = tid >> 5, lane = tid & 31;
    int wm = wid & 1, wn = wid >> 1;
    int row0 = blockIdx.x * 128;

    float acc[4][4][4];
    #pragma unroll
    for (int mt = 0; mt < 4; mt++)
        #pragma unroll
        for (int nt = 0; nt < 4; nt++)
            #pragma unroll
            for (int i = 0; i < 4; i++) acc[mt][nt][i] = 0.f;

    prefetch_w(sm, W_OFF2(0), mat, 0);
    CP_COMMIT();

    ushortt* xhi = (ushortt*)sm;
    ushortt* xlo = (ushortt*)(sm + PS);
    int buf = 0;
    for (int ck = 0; ck < 4; ck++) {
        __syncthreads();   // prev passes done reading X planes + the W buffer we overwrite
        if (ck < 3) {
            prefetch_w(sm, W_OFF2(buf ^ 1), mat, ck + 1);
            CP_COMMIT();
        }
        // convert X chunk (overlaps W cp.async)
        {
            int r = tid >> 1, half = tid & 1;
            int gr = row0 + r;
            int gc = ck * 32 + half * 16;
            uint4 hv = make_uint4(0, 0, 0, 0), lv = make_uint4(0, 0, 0, 0);
            uint4 hv2 = hv, lv2 = lv;
            if (gr < NN) {
                const float* srcp = g_h + gr * DD + gc;
                uint32_t hp[8], lp[8];
                #pragma unroll
                for (int i = 0; i < 8; i++) {
                    float v0 = fmaxf(fmaf(srcp[2 * i], g_scale[gc + 2 * i], g_shift[gc + 2 * i]), 0.f);
                    float v1 = fmaxf(fmaf(srcp[2 * i + 1], g_scale[gc + 2 * i + 1], g_shift[gc + 2 * i + 1]), 0.f);
                    __nv_bfloat16 h0 = __float2bfloat16(v0), h1 = __float2bfloat16(v1);
                    __nv_bfloat16 l0 = __float2bfloat16(v0 - __bfloat162float(h0));
                    __nv_bfloat16 l1 = __float2bfloat16(v1 - __bfloat162float(h1));
                    hp[i] = pack2bf(h0, h1);
                    lp[i] = pack2bf(l0, l1);
                }
                hv = make_uint4(hp[0], hp[1], hp[2], hp[3]);
                hv2 = make_uint4(hp[4], hp[5], hp[6], hp[7]);
                lv = make_uint4(lp[0], lp[1], lp[2], lp[3]);
                lv2 = make_uint4(lp[4], lp[5], lp[6], lp[7]);
            }
            *(uint4*)(xhi + r * PITCH + half * 16)     = hv;
            *(uint4*)(xhi + r * PITCH + half * 16 + 8) = hv2;
            *(uint4*)(xlo + r * PITCH + half * 16)     = lv;
            *(uint4*)(xlo + r * PITCH + half * 16 + 8) = lv2;
        }
        if (ck < 3) CP_WAIT(1); else CP_WAIT(0);
        __syncthreads();
        uint32_t axh = smem_u32(xhi);
        uint32_t axl = smem_u32(xlo);
        uint32_t bwh = smem_u32(sm + W_OFF2(buf));
        uint32_t bwl = bwh + PS;
        do_pass(axh, bwh, wm, wn, lane, acc);
        do_pass(axh, bwl, wm, wn, lane, acc);
        do_pass(axl, bwh, wm, wn, lane, acc);
        buf ^= 1;
    }

    #pragma unroll
    for (int mt = 0; mt < 4; mt++) {
        int r0 = row0 + wm * 64 + mt * 16 + (lane >> 2);
        int r1 = r0 + 8;
        #pragma unroll
        for (int nt = 0; nt < 4; nt++) {
            int c = wn * 32 + nt * 8 + (lane & 3) * 2;
            float b0 = b[c], b1 = b[c + 1];
            float v0 = acc[mt][nt][0] + b0, v1 = acc[mt][nt][1] + b1;
            float v2 = acc[mt][nt][2] + b0, v3 = acc[mt][nt][3] + b1;
            if (do_relu) {
                v0 = fmaxf(v0, 0.f); v1 = fmaxf(v1, 0.f);
                v2 = fmaxf(v2, 0.f); v3 = fmaxf(v3, 0.f);
            }
            if (r0 < NN) *(float2*)(Out + r0 * DD + c) = make_float2(v0, v1);
            if (r1 < NN) *(float2*)(Out + r1 * DD + c) = make_float2(v2, v3);
        }
    }
}

extern "C" void kernel_launch(void* const* d_in, const int* in_sizes, int n_in,
                              void* d_out, int out_size) {
    (void)in_sizes; (void)n_in; (void)out_size;
    const float* x     = (const float*)d_in[0];
    const int*   ei    = (const int*)d_in[1];   // int32 (JAX x64 disabled)
    const float* W1    = (const float*)d_in[2];
    const float* b1    = (const float*)d_in[3];
    const float* gamma = (const float*)d_in[4];
    const float* beta  = (const float*)d_in[5];
    const float* W2    = (const float*)d_in[6];
    const float* b2    = (const float*)d_in[7];
    const float* eps   = (const float*)d_in[8];
    float* out = (float*)d_out;

    const int* src = ei;
    const int* dst = ei + EE;

    cudaFuncSetAttribute(k_gemm1_p, cudaFuncAttributeMaxDynamicSharedMemorySize, SM1_TOT);
    cudaFuncSetAttribute(k_gemm2_p, cudaFuncAttributeMaxDynamicSharedMemorySize, SM2_TOT);

    k_zero_cnt<<<(NN + 255) / 256, 256>>>();
    k_hist<<<(EE + 255) / 256, 256>>>(dst);
    k_scan<<<1, 1024>>>();
    k_fill<<<(EE + 255) / 256, 256>>>(src, dst);
    k_wprep<<<6, 256>>>(W1, W2);

    for (int l = 0; l < 3; l++) {
        int use_ext = (l == 0) ? 1 : 0;
        int internal = (l == 2) ? 0 : 1;
        k_gather<<<(NN * 32 + 255) / 256, 256>>>(x, use_ext, eps + l);
        k_gemm1_p<<<NBT, 256, SM1_TOT>>>(l, b1 + l * DD);
        k_finalize<<<DD, 256>>>(gamma + l * DD, beta + l * DD);
        k_gemm2_p<<<NBT, 256, SM2_TOT>>>(3 + l, b2 + l * DD, out, internal, (l < 2) ? 1 : 0);
    }
}

// round 11
// speedup vs baseline: 1.6493x; 1.0111x over previous
#include <cuda_runtime.h>
#include <cuda_bf16.h>
#include <cstdint>

#define NN 50000
#define DD 128
#define EE 800000
#define NBT 391           // ceil(50000/128) GEMM row tiles

typedef unsigned short ushortt;

// ---------------- scratch (device globals) ----------------
__device__ __align__(16) float g_h[NN * DD];
__device__ __align__(16) float g_x[NN * DD];
__device__ __align__(16) __nv_bfloat16 g_xhi[NN * DD];  // combined feat, bf16 hi plane
__device__ __align__(16) __nv_bfloat16 g_xlo[NN * DD];  // combined feat, bf16 lo plane
__device__ float g_sum[DD];
__device__ float g_sumsq[DD];
// CSR
__device__ int g_cnt[NN];
__device__ int g_row[NN + 1];
__device__ int g_cur[NN];
__device__ int g_adj[EE];
// W images, transposed to [n][k] row-major bf16, hi/lo split; 6 mats
__device__ __align__(16) __nv_bfloat16 g_whi[6 * 16384];
__device__ __align__(16) __nv_bfloat16 g_wlo[6 * 16384];

// ---------------- helpers ----------------
__device__ __forceinline__ uint32_t smem_u32(const void* p) {
    uint32_t a;
    asm("{ .reg .u64 t; cvta.to.shared.u64 t, %1; cvt.u32.u64 %0, t; }" : "=r"(a) : "l"(p));
    return a;
}
__device__ __forceinline__ uint32_t pack2bf(__nv_bfloat16 a, __nv_bfloat16 b) {
    return (uint32_t)__bfloat16_as_ushort(a) | ((uint32_t)__bfloat16_as_ushort(b) << 16);
}
__device__ __forceinline__ void ldm_x4(uint32_t addr, uint32_t* r) {
    asm volatile("ldmatrix.sync.aligned.m8n8.x4.shared.b16 {%0,%1,%2,%3}, [%4];"
        : "=r"(r[0]), "=r"(r[1]), "=r"(r[2]), "=r"(r[3]) : "r"(addr));
}
__device__ __forceinline__ void mma_bf16(float* d, const uint32_t* a, const uint32_t* b) {
    asm volatile("mma.sync.aligned.m16n8k16.row.col.f32.bf16.bf16.f32 "
        "{%0,%1,%2,%3}, {%4,%5,%6,%7}, {%8,%9}, {%0,%1,%2,%3};"
        : "+f"(d[0]), "+f"(d[1]), "+f"(d[2]), "+f"(d[3])
        : "r"(a[0]), "r"(a[1]), "r"(a[2]), "r"(a[3]), "r"(b[0]), "r"(b[1]));
}
__device__ __forceinline__ void cp16(uint32_t sm, const void* g) {
    asm volatile("cp.async.ca.shared.global [%0], [%1], 16;" :: "r"(sm), "l"(g));
}
#define CP_COMMIT() asm volatile("cp.async.commit_group;" ::: "memory")
#define CP_WAIT(n)  asm volatile("cp.async.wait_group %0;" :: "n"(n) : "memory")

#define PITCH 40                 // bf16 per smem plane row (80B: conflict-free ldmatrix)
#define PS 10240                 // plane bytes: 128*PITCH*2
// GEMM1 smem: [Xhi|Xlo](buf0) [Xhi|Xlo](buf1) [Whi|Wlo](buf0) [Whi|Wlo](buf1)
#define X_OFF(b)  ((b) * 2 * PS)
#define W_OFF1(b) (4 * PS + (b) * 2 * PS)
#define SM1_TOT   (8 * PS)       // 81920
// GEMM2 smem: [Xhi|Xlo] [Whi|Wlo](buf0) [Whi|Wlo](buf1) [scale|shift]
#define W_OFF2(b) (2 * PS + (b) * 2 * PS)
#define SC_OFF    (6 * PS)
#define SM2_TOT   (6 * PS + 1024)

// ---------------- CSR build + weight prep ----------------
__global__ void __launch_bounds__(256) k_prep(const float* __restrict__ W1,
                                              const float* __restrict__ W2) {
    if (blockIdx.x < 6) {
        int m = blockIdx.x;
        const float* src = (m < 3) ? (W1 + m * 16384) : (W2 + (m - 3) * 16384);
        __nv_bfloat16* hi = g_whi + m * 16384;
        __nv_bfloat16* lo = g_wlo + m * 16384;
        for (int i = threadIdx.x; i < 16384; i += 256) {
            int k = i >> 7, n = i & 127;
            float v = src[i];
            __nv_bfloat16 h = __float2bfloat16(v);
            __nv_bfloat16 l = __float2bfloat16(v - __bfloat162float(h));
            hi[n * 128 + k] = h;
            lo[n * 128 + k] = l;
        }
    } else {
        int i = (blockIdx.x - 6) * 256 + threadIdx.x;
        if (i < NN) g_cnt[i] = 0;
    }
}
__global__ void k_hist(const int* __restrict__ dst) {
    int e = blockIdx.x * blockDim.x + threadIdx.x;
    if (e < EE) atomicAdd(&g_cnt[dst[e]], 1);
}
__global__ void __launch_bounds__(1024) k_scan() {
    __shared__ int sm[1024];
    const int CH = 49;
    int t = threadIdx.x;
    int beg = t * CH;
    int tot = 0;
    for (int i = beg; i < beg + CH && i < NN; i++) tot += g_cnt[i];
    sm[t] = tot;
    __syncthreads();
    for (int off = 1; off < 1024; off <<= 1) {
        int v = (t >= off) ? sm[t - off] : 0;
        __syncthreads();
        sm[t] += v;
        __syncthreads();
    }
    int base = sm[t] - tot;
    for (int i = beg; i < beg + CH && i < NN; i++) {
        g_row[i] = base; g_cur[i] = 0; base += g_cnt[i];
    }
    if (t == 1023) g_row[NN] = sm[1023];
}
__global__ void k_fill(const int* __restrict__ src, const int* __restrict__ dst) {
    int e = blockIdx.x * blockDim.x + threadIdx.x;
    if (e >= EE) return;
    int d = dst[e];
    int pos = atomicAdd(&g_cur[d], 1);
    g_adj[g_row[d] + pos] = src[e];
}

// ---------------- gather + combine -> bf16 hi/lo planes; zeroes BN stats ----------------
__global__ void k_gather(const float* __restrict__ Xext, int use_ext,
                         const float* __restrict__ epsp) {
    if (blockIdx.x == 0 && threadIdx.x < DD) {
        g_sum[threadIdx.x] = 0.f;
        g_sumsq[threadIdx.x] = 0.f;
    }
    const float* X = use_ext ? Xext : (const float*)g_x;
    int gid = blockIdx.x * blockDim.x + threadIdx.x;
    int node = gid >> 5;
    if (node >= NN) return;
    int lane = gid & 31;
    int beg = g_row[node], end = g_row[node + 1];
    float4 a = make_float4(0.f, 0.f, 0.f, 0.f);
    for (int i = beg; i < end; i++) {
        int s = g_adj[i];
        float4 v = ((const float4*)X)[s * 32 + lane];
        a.x += v.x; a.y += v.y; a.z += v.z; a.w += v.w;
    }
    float4 xv = ((const float4*)X)[node * 32 + lane];
    float pa = a.x * a.x + a.y * a.y + a.z * a.z + a.w * a.w;
    float px = xv.x * xv.x + xv.y * xv.y + xv.z * xv.z + xv.w * xv.w;
    #pragma unroll
    for (int off = 16; off; off >>= 1) {
        pa += __shfl_xor_sync(0xffffffffu, pa, off);
        px += __shfl_xor_sync(0xffffffffu, px, off);
    }
    float ia = 1.f / fmaxf(sqrtf(pa), 1e-12f);
    float ix = (1.f + epsp[0]) / fmaxf(sqrtf(px), 1e-12f);
    float o[4];
    o[0] = a.x * ia + xv.x * ix;
    o[1] = a.y * ia + xv.y * ix;
    o[2] = a.z * ia + xv.z * ix;
    o[3] = a.w * ia + xv.w * ix;
    __nv_bfloat16 h[4], l[4];
    #pragma unroll
    for (int j = 0; j < 4; j++) {
        h[j] = __float2bfloat16(o[j]);
        l[j] = __float2bfloat16(o[j] - __bfloat162float(h[j]));
    }
    *(uint2*)(g_xhi + node * DD + lane * 4) = make_uint2(pack2bf(h[0], h[1]), pack2bf(h[2], h[3]));
    *(uint2*)(g_xlo + node * DD + lane * 4) = make_uint2(pack2bf(l[0], l[1]), pack2bf(l[2], l[3]));
}

// ---------------- shared GEMM machinery (frag mapping validated R8) ----------------
__device__ __forceinline__ void prefetch_w(char* sm, uint32_t woff, int mat, int ck) {
    int tid = threadIdx.x;
    const __nv_bfloat16* gh = g_whi + mat * 16384 + ck * 32;
    const __nv_bfloat16* gl = g_wlo + mat * 16384 + ck * 32;
    uint32_t sh = smem_u32(sm + woff);
    uint32_t sl = sh + PS;
    for (int i = tid; i < 512; i += 256) {
        int row = i >> 2, q = i & 3;
        uint32_t so = (uint32_t)(row * PITCH + q * 8) * 2;
        cp16(sh + so, gh + row * 128 + q * 8);
        cp16(sl + so, gl + row * 128 + q * 8);
    }
}

__device__ __forceinline__ void prefetch_x_guarded(char* sm, uint32_t xoff, int row0, int ck) {
    int tid = threadIdx.x;
    uint32_t sh = smem_u32(sm + xoff);
    uint32_t sl = sh + PS;
    for (int i = tid; i < 512; i += 256) {
        int row = i >> 2, q = i & 3;
        int gr = row0 + row;
        uint32_t so = (uint32_t)(row * PITCH + q * 8) * 2;
        if (gr < NN) {
            cp16(sh + so, g_xhi + gr * DD + ck * 32 + q * 8);
            cp16(sl + so, g_xlo + gr * DD + ck * 32 + q * 8);
        } else {
            uint4 z = make_uint4(0, 0, 0, 0);
            *(uint4*)(sm + xoff + so) = z;
            *(uint4*)(sm + xoff + PS + so) = z;
        }
    }
}

__device__ __forceinline__ void do_pass(uint32_t abase, uint32_t bbase,
                                        int wm, int wn, int lane, float acc[4][4][4]) {
    #pragma unroll
    for (int ks = 0; ks < 2; ks++) {
        uint32_t af[4][4];
        #pragma unroll
        for (int mt = 0; mt < 4; mt++) {
            int row = wm * 64 + mt * 16 + (lane & 7) + ((lane >> 3) & 1) * 8;
            int col = ks * 16 + ((lane >> 4) & 1) * 8;
            ldm_x4(abase + (row * PITCH + col) * 2, af[mt]);
        }
        uint32_t bf[4][2];
        #pragma unroll
        for (int jp = 0; jp < 2; jp++) {
            int n = wn * 32 + jp * 16 + ((lane >> 4) & 1) * 8 + (lane & 7);
            int col = ks * 16 + ((lane >> 3) & 1) * 8;
            uint32_t r4[4];
            ldm_x4(bbase + (n * PITCH + col) * 2, r4);
            bf[jp * 2][0] = r4[0]; bf[jp * 2][1] = r4[1];
            bf[jp * 2 + 1][0] = r4[2]; bf[jp * 2 + 1][1] = r4[3];
        }
        #pragma unroll
        for (int mt = 0; mt < 4; mt++)
            #pragma unroll
            for (int nt = 0; nt < 4; nt++)
                mma_bf16(acc[mt][nt], af[mt], bf[nt]);
    }
}

extern __shared__ __align__(16) char dsm[];

// ---------------- GEMM1: h = comb @ W1 + b1 -> g_h, BN stats via atomics ----------------
__global__ void __launch_bounds__(256) k_gemm1_p(int mat, const float* __restrict__ b) {
    char* sm = dsm;
    int tid = threadIdx.x;
    int wid = tid >> 5, lane = tid & 31;
    int wm = wid & 1, wn = wid >> 1;
    int row0 = blockIdx.x * 128;

    float acc[4][4][4];
    #pragma unroll
    for (int mt = 0; mt < 4; mt++)
        #pragma unroll
        for (int nt = 0; nt < 4; nt++)
            #pragma unroll
            for (int i = 0; i < 4; i++) acc[mt][nt][i] = 0.f;

    prefetch_x_guarded(sm, X_OFF(0), row0, 0);
    prefetch_w(sm, W_OFF1(0), mat, 0);
    CP_COMMIT();

    int buf = 0;
    for (int ck = 0; ck < 4; ck++) {
        __syncthreads();
        if (ck < 3) {
            prefetch_x_guarded(sm, X_OFF(buf ^ 1), row0, ck + 1);
            prefetch_w(sm, W_OFF1(buf ^ 1), mat, ck + 1);
            CP_COMMIT();
            CP_WAIT(1);
        } else {
            CP_WAIT(0);
        }
        __syncthreads();
        uint32_t axh = smem_u32(sm + X_OFF(buf));
        uint32_t axl = axh + PS;
        uint32_t bwh = smem_u32(sm + W_OFF1(buf));
        uint32_t bwl = bwh + PS;
        do_pass(axh, bwh, wm, wn, lane, acc);   // hi*hi
        do_pass(axh, bwl, wm, wn, lane, acc);   // hi*lo
        do_pass(axl, bwh, wm, wn, lane, acc);   // lo*hi
        buf ^= 1;
    }

    // epilogue: bias, store h, BN partials -> global atomics
    float ls[4][2], lq[4][2];
    #pragma unroll
    for (int nt = 0; nt < 4; nt++) { ls[nt][0] = ls[nt][1] = lq[nt][0] = lq[nt][1] = 0.f; }
    #pragma unroll
    for (int mt = 0; mt < 4; mt++) {
        int r0 = row0 + wm * 64 + mt * 16 + (lane >> 2);
        int r1 = r0 + 8;
        #pragma unroll
        for (int nt = 0; nt < 4; nt++) {
            int c = wn * 32 + nt * 8 + (lane & 3) * 2;
            float b0 = b[c], b1 = b[c + 1];
            float v0 = acc[mt][nt][0] + b0, v1 = acc[mt][nt][1] + b1;
            float v2 = acc[mt][nt][2] + b0, v3 = acc[mt][nt][3] + b1;
            if (r0 < NN) {
                *(float2*)(g_h + r0 * DD + c) = make_float2(v0, v1);
                ls[nt][0] += v0; ls[nt][1] += v1;
                lq[nt][0] += v0 * v0; lq[nt][1] += v1 * v1;
            }
            if (r1 < NN) {
                *(float2*)(g_h + r1 * DD + c) = make_float2(v2, v3);
                ls[nt][0] += v2; ls[nt][1] += v3;
                lq[nt][0] += v2 * v2; lq[nt][1] += v3 * v3;
            }
        }
    }
    #pragma unroll
    for (int off = 4; off <= 16; off <<= 1) {
        #pragma unroll
        for (int nt = 0; nt < 4; nt++) {
            ls[nt][0] += __shfl_xor_sync(0xffffffffu, ls[nt][0], off);
            ls[nt][1] += __shfl_xor_sync(0xffffffffu, ls[nt][1], off);
            lq[nt][0] += __shfl_xor_sync(0xffffffffu, lq[nt][0], off);
            lq[nt][1] += __shfl_xor_sync(0xffffffffu, lq[nt][1], off);
        }
    }
    __syncthreads();
    float* ssum = (float*)sm;
    float* ssq  = ssum + 256;
    if (lane < 4) {
        #pragma unroll
        for (int nt = 0; nt < 4; nt++) {
            ssum[wid * 32 + nt * 8 + lane * 2]     = ls[nt][0];
            ssum[wid * 32 + nt * 8 + lane * 2 + 1] = ls[nt][1];
            ssq[wid * 32 + nt * 8 + lane * 2]      = lq[nt][0];
            ssq[wid * 32 + nt * 8 + lane * 2 + 1]  = lq[nt][1];
        }
    }
    __syncthreads();
    if (tid < DD) {
        int w0 = (tid >> 5) * 2;
        float s = ssum[w0 * 32 + (tid & 31)] + ssum[(w0 + 1) * 32 + (tid & 31)];
        float q = ssq[w0 * 32 + (tid & 31)] + ssq[(w0 + 1) * 32 + (tid & 31)];
        atomicAdd(&g_sum[tid], s);
        atomicAdd(&g_sumsq[tid], q);
    }
}

// ---------------- GEMM2: out = relu?(bn_relu(h) @ W2 + b2); BN finalize inline ----------------
__global__ void __launch_bounds__(256) k_gemm2_p(int mat, const float* __restrict__ gamma,
                                                 const float* __restrict__ beta,
                                                 const float* __restrict__ b,
                                                 float* __restrict__ OutExt,
                                                 int internal, int do_relu) {
    char* sm = dsm;
    float* Out = internal ? (float*)g_x : OutExt;
    int tid = threadIdx.x;
    int wid = tid >> 5, lane = tid & 31;
    int wm = wid & 1, wn = wid >> 1;
    int row0 = blockIdx.x * 128;

    float acc[4][4][4];
    #pragma unroll
    for (int mt = 0; mt < 4; mt++)
        #pragma unroll
        for (int nt = 0; nt < 4; nt++)
            #pragma unroll
            for (int i = 0; i < 4; i++) acc[mt][nt][i] = 0.f;

    prefetch_w(sm, W_OFF2(0), mat, 0);
    CP_COMMIT();

    // inline BN finalize: scale/shift into smem (overlaps W prefetch)
    float* sscale = (float*)(sm + SC_OFF);
    float* sshift = sscale + DD;
    if (tid < DD) {
        float mean = g_sum[tid] * (1.f / NN);
        float var  = g_sumsq[tid] * (1.f / NN) - mean * mean;
        float sc = gamma[tid] * rsqrtf(var + 1e-5f);
        sscale[tid] = sc;
        sshift[tid] = beta[tid] - mean * sc;
    }

    ushortt* xhi = (ushortt*)sm;
    ushortt* xlo = (ushortt*)(sm + PS);
    int buf = 0;
    for (int ck = 0; ck < 4; ck++) {
        __syncthreads();   // prev passes done; also publishes sscale/sshift at ck=0
        if (ck < 3) {
            prefetch_w(sm, W_OFF2(buf ^ 1), mat, ck + 1);
            CP_COMMIT();
        }
        // convert X chunk (overlaps W cp.async)
        {
            int r = tid >> 1, half = tid & 1;
            int gr = row0 + r;
            int gc = ck * 32 + half * 16;
            uint4 hv = make_uint4(0, 0, 0, 0), lv = make_uint4(0, 0, 0, 0);
            uint4 hv2 = hv, lv2 = lv;
            if (gr < NN) {
                const float* srcp = g_h + gr * DD + gc;
                uint32_t hp[8], lp[8];
                #pragma unroll
                for (int i = 0; i < 8; i++) {
                    float v0 = fmaxf(fmaf(srcp[2 * i], sscale[gc + 2 * i], sshift[gc + 2 * i]), 0.f);
                    float v1 = fmaxf(fmaf(srcp[2 * i + 1], sscale[gc + 2 * i + 1], sshift[gc + 2 * i + 1]), 0.f);
                    __nv_bfloat16 h0 = __float2bfloat16(v0), h1 = __float2bfloat16(v1);
                    __nv_bfloat16 l0 = __float2bfloat16(v0 - __bfloat162float(h0));
                    __nv_bfloat16 l1 = __float2bfloat16(v1 - __bfloat162float(h1));
                    hp[i] = pack2bf(h0, h1);
                    lp[i] = pack2bf(l0, l1);
                }
                hv = make_uint4(hp[0], hp[1], hp[2], hp[3]);
                hv2 = make_uint4(hp[4], hp[5], hp[6], hp[7]);
                lv = make_uint4(lp[0], lp[1], lp[2], lp[3]);
                lv2 = make_uint4(lp[4], lp[5], lp[6], lp[7]);
            }
            *(uint4*)(xhi + r * PITCH + half * 16)     = hv;
            *(uint4*)(xhi + r * PITCH + half * 16 + 8) = hv2;
            *(uint4*)(xlo + r * PITCH + half * 16)     = lv;
            *(uint4*)(xlo + r * PITCH + half * 16 + 8) = lv2;
        }
        if (ck < 3) CP_WAIT(1); else CP_WAIT(0);
        __syncthreads();
        uint32_t axh = smem_u32(xhi);
        uint32_t axl = smem_u32(xlo);
        uint32_t bwh = smem_u32(sm + W_OFF2(buf));
        uint32_t bwl = bwh + PS;
        do_pass(axh, bwh, wm, wn, lane, acc);
        do_pass(axh, bwl, wm, wn, lane, acc);
        do_pass(axl, bwh, wm, wn, lane, acc);
        buf ^= 1;
    }

    #pragma unroll
    for (int mt = 0; mt < 4; mt++) {
        int r0 = row0 + wm * 64 + mt * 16 + (lane >> 2);
        int r1 = r0 + 8;
        #pragma unroll
        for (int nt = 0; nt < 4; nt++) {
            int c = wn * 32 + nt * 8 + (lane & 3) * 2;
            float b0 = b[c], b1 = b[c + 1];
            float v0 = acc[mt][nt][0] + b0, v1 = acc[mt][nt][1] + b1;
            float v2 = acc[mt][nt][2] + b0, v3 = acc[mt][nt][3] + b1;
            if (do_relu) {
                v0 = fmaxf(v0, 0.f); v1 = fmaxf(v1, 0.f);
                v2 = fmaxf(v2, 0.f); v3 = fmaxf(v3, 0.f);
            }
            if (r0 < NN) *(float2*)(Out + r0 * DD + c) = make_float2(v0, v1);
            if (r1 < NN) *(float2*)(Out + r1 * DD + c) = make_float2(v2, v3);
        }
    }
}

extern "C" void kernel_launch(void* const* d_in, const int* in_sizes, int n_in,
                              void* d_out, int out_size) {
    (void)in_sizes; (void)n_in; (void)out_size;
    const float* x     = (const float*)d_in[0];
    const int*   ei    = (const int*)d_in[1];   // int32 (JAX x64 disabled)
    const float* W1    = (const float*)d_in[2];
    const float* b1    = (const float*)d_in[3];
    const float* gamma = (const float*)d_in[4];
    const float* beta  = (const float*)d_in[5];
    const float* W2    = (const float*)d_in[6];
    const float* b2    = (const float*)d_in[7];
    const float* eps   = (const float*)d_in[8];
    float* out = (float*)d_out;

    const int* src = ei;
    const int* dst = ei + EE;

    cudaFuncSetAttribute(k_gemm1_p, cudaFuncAttributeMaxDynamicSharedMemorySize, SM1_TOT);
    cudaFuncSetAttribute(k_gemm2_p, cudaFuncAttributeMaxDynamicSharedMemorySize, SM2_TOT);

    k_prep<<<6 + (NN + 255) / 256, 256>>>(W1, W2);
    k_hist<<<(EE + 255) / 256, 256>>>(dst);
    k_scan<<<1, 1024>>>();
    k_fill<<<(EE + 255) / 256, 256>>>(src, dst);

    for (int l = 0; l < 3; l++) {
        int use_ext = (l == 0) ? 1 : 0;
        int internal = (l == 2) ? 0 : 1;
        k_gather<<<(NN * 32 + 255) / 256, 256>>>(x, use_ext, eps + l);
        k_gemm1_p<<<NBT, 256, SM1_TOT>>>(l, b1 + l * DD);
        k_gemm2_p<<<NBT, 256, SM2_TOT>>>(3 + l, gamma + l * DD, beta + l * DD,
                                         b2 + l * DD, out, internal, (l < 2) ? 1 : 0);
    }
}